// round 13
// baseline (speedup 1.0000x reference)
#include <cuda_runtime.h>
#include <cuda_bf16.h>
#include <cstdint>

// VectorQuantizer N=65536, K=8192, D=256.
// R12: bf16 mma.sync filter; e/z streamed with cp.async.bulk (1 instr / 32KB
// tile) into XOR-pre-swizzled global layout; BM=256 halves waves+traffic.
// Exact fp32 rescore replicating R2 arithmetic bit-for-bit (rel_err 0.0).

typedef unsigned long long u64;
typedef uint32_t u32;

#define NN     65536
#define KC     8192
#define DD     256
#define BM     256
#define BN     64
#define NTILES (KC / BN)     // 128
#define NTHR   512
#define CAP    14
#define WIN    6e-4f

// bf16 tiles stored PRE-SWIZZLED: 16B chunk c of row r lives at chunk (c^(r&7))
__device__ uint4 g_zbf4[(size_t)NN * 32];   // 32 MB
__device__ uint4 g_ebf4[(size_t)KC * 32];   // 4 MB
__device__ float g_z2[NN];
__device__ float g_e2[KC];

// smem byte offsets
#define SA    0                         // 256 rows * 512B = 131072
#define SB0   131072                    // 64 * 512 = 32768
#define SB1   163840
#define SZ2   196608                    // 256*4
#define SMIN  197632
#define SCNT  198656
#define SCD   199680                    // 256*14*4 = 14336
#define SCK   214016
#define SFI   228352                    // 256*4
#define SMBAR 229376                    // 3 mbarriers
#define STOT  229440

__device__ __forceinline__ u32 s2u(const void* p) {
    u32 a;
    asm("{ .reg .u64 t; cvta.to.shared.u64 t, %1; cvt.u32.u64 %0, t; }"
        : "=r"(a) : "l"(p));
    return a;
}
__device__ __forceinline__ void ldsm4(u32* r, u32 saddr) {
    asm volatile("ldmatrix.sync.aligned.m8n8.x4.shared.b16 {%0,%1,%2,%3}, [%4];"
                 : "=r"(r[0]), "=r"(r[1]), "=r"(r[2]), "=r"(r[3]) : "r"(saddr));
}
__device__ __forceinline__ void mma16816(float* c, const u32* a, const u32* b) {
    asm volatile("mma.sync.aligned.m16n8k16.row.col.f32.bf16.bf16.f32 "
                 "{%0,%1,%2,%3}, {%4,%5,%6,%7}, {%8,%9}, {%0,%1,%2,%3};"
                 : "+f"(c[0]), "+f"(c[1]), "+f"(c[2]), "+f"(c[3])
                 : "r"(a[0]), "r"(a[1]), "r"(a[2]), "r"(a[3]),
                   "r"(b[0]), "r"(b[1]));
}
#define MBAR_INIT(a,c) asm volatile("mbarrier.init.shared.b64 [%0], %1;" \
                                    :: "r"(a), "r"(c) : "memory")
#define EXPECT_TX(a,b) asm volatile("mbarrier.arrive.expect_tx.shared.b64 _, [%0], %1;" \
                                    :: "r"(a), "r"(b) : "memory")
#define BULK_G2S(dst,src,bytes,mbar) \
    asm volatile("cp.async.bulk.shared::cluster.global.mbarrier::complete_tx::bytes " \
                 "[%0], [%1], %2, [%3];" \
                 :: "r"(dst), "l"(src), "r"(bytes), "r"(mbar) : "memory")

__device__ __forceinline__ void mbar_wait(u32 mbar, u32 parity) {
    u32 done;
    asm volatile("{\n\t.reg .pred p;\n\t"
                 "mbarrier.try_wait.parity.acquire.cta.shared::cta.b64 p, [%1], %2;\n\t"
                 "selp.b32 %0,1,0,p;\n\t}" : "=r"(done) : "r"(mbar), "r"(parity) : "memory");
    if (!done) {
        asm volatile("{\n\t.reg .pred P1;\n\t"
                     "W_%=:\n\t"
                     "mbarrier.try_wait.parity.acquire.cta.shared::cta.b64 P1, [%0], %1, 0x989680;\n\t"
                     "@P1 bra.uni D_%=;\n\t"
                     "bra.uni W_%=;\n\t"
                     "D_%=:\n\t}" :: "r"(mbar), "r"(parity) : "memory");
    }
}

// ---------------- prep: bf16-convert into swizzled-linear layout + z2/e2 ----------------
__global__ void prep_all(const float* __restrict__ z, const float* __restrict__ emb) {
    int b = blockIdx.x, lane = threadIdx.x;     // lane = 16B chunk index 0..31
    const float* r;
    uint4* dst4;
    if (b < KC) { r = emb + (size_t)b * DD; dst4 = g_ebf4 + (size_t)b * 32; }
    else        { int n = b - KC; r = z + (size_t)n * DD; dst4 = g_zbf4 + (size_t)n * 32; }
    {
        const float* p = r + lane * 8;
        __nv_bfloat162 h0 = __floats2bfloat162_rn(p[0], p[1]);
        __nv_bfloat162 h1 = __floats2bfloat162_rn(p[2], p[3]);
        __nv_bfloat162 h2 = __floats2bfloat162_rn(p[4], p[5]);
        __nv_bfloat162 h3 = __floats2bfloat162_rn(p[6], p[7]);
        uint4 v;
        v.x = *(u32*)&h0; v.y = *(u32*)&h1; v.z = *(u32*)&h2; v.w = *(u32*)&h3;
        dst4[lane ^ (b & 7)] = v;               // b&7 == row&7 (rows are row-major)
    }
    if (lane == 0) {
        float s = 0.f;
        #pragma unroll 8
        for (int d = 0; d < DD; ++d) s = __fadd_rn(s, __fmul_rn(r[d], r[d]));
        if (b < KC) g_e2[b] = s; else g_z2[b - KC] = s;
    }
}

// ---------------- main kernel ----------------
__global__ __launch_bounds__(NTHR, 1)
void vq_main(const float* __restrict__ z, const float* __restrict__ emb,
             float* __restrict__ oq, float* __restrict__ ost,
             float* __restrict__ oidx)
{
    extern __shared__ char sm[];
    const u32 smb = s2u(sm);
    float* z2s    = (float*)(sm + SZ2);
    int*   rowMin = (int*)(sm + SMIN);
    int*   cnt    = (int*)(sm + SCNT);
    float* candD  = (float*)(sm + SCD);
    int*   candK  = (int*)(sm + SCK);
    int*   fidx   = (int*)(sm + SFI);

    const int tid  = threadIdx.x;
    const int wid  = tid >> 5;
    const int lane = tid & 31;
    const int rowbase = blockIdx.x * BM;
    const int Rw = (wid & 7) * 32;      // 8 warps over M=256
    const int Cw = (wid >> 3) * 32;     // 2 warps over N=64

    if (tid < BM) {
        rowMin[tid] = 0x7f7fffff;
        cnt[tid] = 0;
        z2s[tid] = g_z2[rowbase + tid];
    }
    const u32 mb0 = smb + SMBAR, mb1 = smb + SMBAR + 8, mbA = smb + SMBAR + 16;
    if (tid == 0) { MBAR_INIT(mb0, 1); MBAR_INIT(mb1, 1); MBAR_INIT(mbA, 1); }
    __syncthreads();

    if (tid == 0) {
        EXPECT_TX(mbA, 131072);
        BULK_G2S(smb + SA, (const char*)(g_zbf4 + (size_t)rowbase * 32), 131072, mbA);
        EXPECT_TX(mb0, 32768);
        BULK_G2S(smb + SB0, (const char*)g_ebf4, 32768, mb0);
    }
    mbar_wait(mbA, 0);

    // ldmatrix lane geometry (pre-swizzled layout: chunk ^= row&7)
    const int lrA = (lane & 7) + 8 * ((lane >> 3) & 1);
    const int khA = lane >> 4;                   // k-chunk half for A
    const int rowA = Rw + lrA;
    const u32 baseA = smb + SA + (u32)rowA * 512;
    const int xA = rowA & 7;
    const int lrB = (lane & 7) + 8 * (lane >> 4);
    const int khB = (lane >> 3) & 1;
    const int rowB = Cw + lrB;
    const u32 offB = (u32)rowB * 512;
    const int xB = rowB & 7;

    for (int t = 0; t < NTILES; ++t) {
        if (t + 1 < NTILES && tid == 0) {
            u32 mb = ((t + 1) & 1) ? mb1 : mb0;
            EXPECT_TX(mb, 32768);
            BULK_G2S(smb + (((t + 1) & 1) ? SB1 : SB0),
                     (const char*)(g_ebf4 + (size_t)(t + 1) * BN * 32), 32768, mb);
        }
        mbar_wait((t & 1) ? mb1 : mb0, (t >> 1) & 1);

        const u32 baseB = smb + ((t & 1) ? SB1 : SB0) + offB;

        float acc[2][4][4];
        #pragma unroll
        for (int mi = 0; mi < 2; ++mi)
            #pragma unroll
            for (int ni = 0; ni < 4; ++ni)
                #pragma unroll
                for (int c = 0; c < 4; ++c) acc[mi][ni][c] = 0.f;

        #pragma unroll 4
        for (int ks = 0; ks < 16; ++ks) {
            u32 aT[2][4], bT[2][4];
            u32 ca = (u32)(((2 * ks + khA) ^ xA) << 4);
            u32 cb2 = (u32)(((2 * ks + khB) ^ xB) << 4);
            ldsm4(aT[0], baseA + ca);
            ldsm4(aT[1], baseA + 8192 + ca);
            ldsm4(bT[0], baseB + cb2);
            ldsm4(bT[1], baseB + 8192 + cb2);
            #pragma unroll
            for (int mi = 0; mi < 2; ++mi) {
                mma16816(acc[mi][0], aT[mi], &bT[0][0]);
                mma16816(acc[mi][1], aT[mi], &bT[0][2]);
                mma16816(acc[mi][2], aT[mi], &bT[1][0]);
                mma16816(acc[mi][3], aT[mi], &bT[1][2]);
            }
        }

        // ---- epilogue: dv in-place, row-min update, windowed inserts ----
        int cb = t * BN;
        float e2loc[4][2];
        #pragma unroll
        for (int ni = 0; ni < 4; ++ni) {
            float2 v = __ldg((const float2*)(g_e2 + cb + Cw + ni * 8 + (lane & 3) * 2));
            e2loc[ni][0] = v.x; e2loc[ni][1] = v.y;
        }
        #pragma unroll
        for (int mi = 0; mi < 2; ++mi) {
            #pragma unroll
            for (int s = 0; s < 2; ++s) {
                int r = Rw + mi * 16 + (lane >> 2) + 8 * s;
                float z2v = z2s[r];
                float mn = 3.4e38f;
                #pragma unroll
                for (int ni = 0; ni < 4; ++ni) {
                    #pragma unroll
                    for (int q = 0; q < 2; ++q) {
                        float dv = fmaf(-2.f, acc[mi][ni][2 * s + q], z2v + e2loc[ni][q]);
                        acc[mi][ni][2 * s + q] = dv;
                        mn = fminf(mn, dv);
                    }
                }
                if (__float_as_int(mn) < rowMin[r])
                    atomicMin(&rowMin[r], __float_as_int(mn));
            }
        }
        if (t == 0) __syncthreads();   // tile 0: establish thresholds first
        #pragma unroll
        for (int mi = 0; mi < 2; ++mi) {
            #pragma unroll
            for (int s = 0; s < 2; ++s) {
                int r = Rw + mi * 16 + (lane >> 2) + 8 * s;
                float thr = __int_as_float(rowMin[r]) + WIN;
                #pragma unroll
                for (int ni = 0; ni < 4; ++ni) {
                    #pragma unroll
                    for (int q = 0; q < 2; ++q) {
                        float dv = acc[mi][ni][2 * s + q];
                        if (dv <= thr) {
                            int pos = atomicAdd(&cnt[r], 1);
                            if (pos < CAP) {
                                candD[r * CAP + pos] = dv;
                                candK[r * CAP + pos] = cb + Cw + ni * 8 + (lane & 3) * 2 + q;
                            }
                        }
                    }
                }
            }
        }
        __syncthreads();
    }

    // ---- exact rescore (replicates R2 arithmetic exactly) ----
    if (tid < BM) {
        int r = tid;
        size_t n = (size_t)rowbase + r;
        int c = cnt[r];
        if (c > CAP) {
            fidx[r] = -1;
        } else {
            float thrF = __int_as_float(rowMin[r]) + WIN;
            float z2e = g_z2[n];
            const float* zr = z + n * DD;
            float bd = 0.f; int bk = -1;
            for (int i = 0; i < c; ++i) {
                if (candD[r * CAP + i] > thrF) continue;
                int k = candK[r * CAP + i];
                const float* er = emb + (size_t)k * DD;
                float lo = 0.f, hi = 0.f;
                #pragma unroll 4
                for (int d2 = 0; d2 < DD / 2; ++d2) {
                    lo = __fmaf_rn(__ldg(zr + 2 * d2),     __ldg(er + 2 * d2),     lo);
                    hi = __fmaf_rn(__ldg(zr + 2 * d2 + 1), __ldg(er + 2 * d2 + 1), hi);
                }
                float dot = __fadd_rn(lo, hi);
                float tt  = __fadd_rn(z2e, g_e2[k]);
                float dd  = __fadd_rn(tt, -2.0f * dot);
                if (bk < 0 || dd < bd || (dd == bd && k < bk)) { bd = dd; bk = k; }
            }
            fidx[r] = bk;
        }
    }
    __syncthreads();

    // ---- overflow fallback: full exact scan (cold) ----
    {
        float* redD = (float*)(sm + SB0);
        int*   redI = (int*)(sm + SB0 + NTHR * 4);
        for (int r = 0; r < BM; ++r) {
            if (fidx[r] != -1) continue;
            size_t n = (size_t)rowbase + r;
            const float* zr = z + n * DD;
            float z2e = g_z2[n];
            float bd = 0.f; int bk = -1;
            for (int k = tid; k < KC; k += NTHR) {
                const float* er = emb + (size_t)k * DD;
                float lo = 0.f, hi = 0.f;
                #pragma unroll 4
                for (int d2 = 0; d2 < DD / 2; ++d2) {
                    lo = __fmaf_rn(zr[2 * d2],     er[2 * d2],     lo);
                    hi = __fmaf_rn(zr[2 * d2 + 1], er[2 * d2 + 1], hi);
                }
                float dot = __fadd_rn(lo, hi);
                float dd  = __fadd_rn(__fadd_rn(z2e, g_e2[k]), -2.0f * dot);
                if (bk < 0 || dd < bd || (dd == bd && k < bk)) { bd = dd; bk = k; }
            }
            redD[tid] = bd; redI[tid] = bk;
            __syncthreads();
            if (tid == 0) {
                float B = redD[0]; int K2 = redI[0];
                for (int s2 = 1; s2 < NTHR; ++s2) {
                    float d = redD[s2]; int k2 = redI[s2];
                    if (k2 >= 0 && (K2 < 0 || d < B || (d == B && k2 < K2))) { B = d; K2 = k2; }
                }
                fidx[r] = K2;
            }
            __syncthreads();
        }
    }
    __syncthreads();

    // ---- outputs (512 threads: 2 rows per pass) ----
    for (int rr = 0; rr < BM; rr += 2) {
        int    r   = rr + (tid >> 8);
        int    c   = tid & 255;
        int    idx = fidx[r];
        size_t n   = (size_t)rowbase + r;
        float  qv  = __ldg(emb + (size_t)idx * DD + c);
        float  zv  = __ldg(z + n * DD + c);
        if (oq)  oq[n * DD + c]  = qv;
        if (ost) ost[n * DD + c] = __fadd_rn(__fadd_rn(qv, -zv), zv);
    }
    if (oidx && tid < BM)
        oidx[(size_t)rowbase + tid] = (float)fidx[tid];
}

extern "C" void kernel_launch(void* const* d_in, const int* in_sizes, int n_in,
                              void* d_out, int out_size)
{
    const float* z   = (const float*)d_in[0];
    const float* emb = (const float*)d_in[1];
    float* out = (float*)d_out;

    const int N = in_sizes[0] / DD;
    const size_t ND = (size_t)N * DD;

    float *oq = nullptr, *ost = nullptr, *oidx = nullptr;
    long osz = (long)out_size;
    if (osz >= (long)(2 * ND + N)) { oq = out; ost = out + ND; oidx = out + 2 * ND; }
    else if (osz == (long)(ND + N)) { oq = out; oidx = out + ND; }
    else if (osz == (long)ND)       { oq = out; }
    else if (osz == (long)N)        { oidx = out; }
    else                            { oq = out; }

    prep_all<<<KC + N, 32>>>(z, emb);

    cudaFuncSetAttribute(vq_main, cudaFuncAttributeMaxDynamicSharedMemorySize, STOT);
    vq_main<<<N / BM, NTHR, STOT>>>(z, emb, oq, ost, oidx);
}

// round 14
// speedup vs baseline: 126.3677x; 126.3677x over previous
#include <cuda_runtime.h>
#include <cuda_bf16.h>
#include <cstdint>

// VectorQuantizer N=65536, K=8192, D=256.
// R13: R10 structure (BM=128,BN=64,16 warps,m32n16/warp, CAP back to 40 --
// R11/R12 regressions were overflow-fallback storms from CAP<32) with
// cp.async.bulk streams + XOR-pre-swizzled global bf16 layout (validated in
// R12). Exact fp32 rescore replicating R2 arithmetic bit-for-bit (rel_err 0.0).

typedef unsigned long long u64;
typedef uint32_t u32;

#define NN     65536
#define KC     8192
#define DD     256
#define BM     128
#define BN     64
#define NTILES (KC / BN)     // 128
#define NTHR   512
#define CAP    40
#define WIN    6e-4f

// bf16 rows stored PRE-SWIZZLED: 16B chunk c of row r lives at chunk (c^(r&7))
__device__ uint4 g_zbf4[(size_t)NN * 32];   // 32 MB
__device__ uint4 g_ebf4[(size_t)KC * 32];   // 4 MB
__device__ float g_z2[NN];
__device__ float g_e2[KC];

// smem byte offsets
#define SA    0                         // 128 rows * 512B = 65536
#define SB0   65536                     // 64 * 512 = 32768
#define SB1   98304
#define SZ2   131072                    // 128*4
#define SMIN  131584
#define SCNT  132096
#define SCD   132608                    // 128*40*4 = 20480
#define SCK   153088                    // 20480
#define SFI   173568                    // 512
#define SMBAR 174080                    // 3 mbarriers
#define STOT  174144

__device__ __forceinline__ u32 s2u(const void* p) {
    u32 a;
    asm("{ .reg .u64 t; cvta.to.shared.u64 t, %1; cvt.u32.u64 %0, t; }"
        : "=r"(a) : "l"(p));
    return a;
}
__device__ __forceinline__ void ldsm4(u32* r, u32 saddr) {
    asm volatile("ldmatrix.sync.aligned.m8n8.x4.shared.b16 {%0,%1,%2,%3}, [%4];"
                 : "=r"(r[0]), "=r"(r[1]), "=r"(r[2]), "=r"(r[3]) : "r"(saddr));
}
__device__ __forceinline__ void mma16816(float* c, const u32* a, const u32* b) {
    asm volatile("mma.sync.aligned.m16n8k16.row.col.f32.bf16.bf16.f32 "
                 "{%0,%1,%2,%3}, {%4,%5,%6,%7}, {%8,%9}, {%0,%1,%2,%3};"
                 : "+f"(c[0]), "+f"(c[1]), "+f"(c[2]), "+f"(c[3])
                 : "r"(a[0]), "r"(a[1]), "r"(a[2]), "r"(a[3]),
                   "r"(b[0]), "r"(b[1]));
}
#define MBAR_INIT(a,c) asm volatile("mbarrier.init.shared.b64 [%0], %1;" \
                                    :: "r"(a), "r"(c) : "memory")
#define EXPECT_TX(a,b) asm volatile("mbarrier.arrive.expect_tx.shared.b64 _, [%0], %1;" \
                                    :: "r"(a), "r"(b) : "memory")
#define BULK_G2S(dst,src,bytes,mbar) \
    asm volatile("cp.async.bulk.shared::cluster.global.mbarrier::complete_tx::bytes " \
                 "[%0], [%1], %2, [%3];" \
                 :: "r"(dst), "l"(src), "r"(bytes), "r"(mbar) : "memory")

__device__ __forceinline__ void mbar_wait(u32 mbar, u32 parity) {
    u32 done;
    asm volatile("{\n\t.reg .pred p;\n\t"
                 "mbarrier.try_wait.parity.acquire.cta.shared::cta.b64 p, [%1], %2;\n\t"
                 "selp.b32 %0,1,0,p;\n\t}" : "=r"(done) : "r"(mbar), "r"(parity) : "memory");
    if (!done) {
        asm volatile("{\n\t.reg .pred P1;\n\t"
                     "W_%=:\n\t"
                     "mbarrier.try_wait.parity.acquire.cta.shared::cta.b64 P1, [%0], %1, 0x989680;\n\t"
                     "@P1 bra.uni D_%=;\n\t"
                     "bra.uni W_%=;\n\t"
                     "D_%=:\n\t}" :: "r"(mbar), "r"(parity) : "memory");
    }
}

// ---------------- prep: bf16-convert into swizzled-linear layout + z2/e2 ----------------
__global__ void prep_all(const float* __restrict__ z, const float* __restrict__ emb) {
    int b = blockIdx.x, lane = threadIdx.x;     // lane = 16B chunk index 0..31
    const float* r;
    uint4* dst4;
    if (b < KC) { r = emb + (size_t)b * DD; dst4 = g_ebf4 + (size_t)b * 32; }
    else        { int n = b - KC; r = z + (size_t)n * DD; dst4 = g_zbf4 + (size_t)n * 32; }
    {
        const float* p = r + lane * 8;
        __nv_bfloat162 h0 = __floats2bfloat162_rn(p[0], p[1]);
        __nv_bfloat162 h1 = __floats2bfloat162_rn(p[2], p[3]);
        __nv_bfloat162 h2 = __floats2bfloat162_rn(p[4], p[5]);
        __nv_bfloat162 h3 = __floats2bfloat162_rn(p[6], p[7]);
        uint4 v;
        v.x = *(u32*)&h0; v.y = *(u32*)&h1; v.z = *(u32*)&h2; v.w = *(u32*)&h3;
        dst4[lane ^ (b & 7)] = v;               // b&7 == row&7
    }
    if (lane == 0) {
        float s = 0.f;
        #pragma unroll 8
        for (int d = 0; d < DD; ++d) s = __fadd_rn(s, __fmul_rn(r[d], r[d]));
        if (b < KC) g_e2[b] = s; else g_z2[b - KC] = s;
    }
}

// ---------------- main kernel ----------------
__global__ __launch_bounds__(NTHR, 1)
void vq_main(const float* __restrict__ z, const float* __restrict__ emb,
             float* __restrict__ oq, float* __restrict__ ost,
             float* __restrict__ oidx)
{
    extern __shared__ char sm[];
    const u32 smb = s2u(sm);
    float* z2s    = (float*)(sm + SZ2);
    int*   rowMin = (int*)(sm + SMIN);
    int*   cnt    = (int*)(sm + SCNT);
    float* candD  = (float*)(sm + SCD);
    int*   candK  = (int*)(sm + SCK);
    int*   fidx   = (int*)(sm + SFI);

    const int tid  = threadIdx.x;
    const int wid  = tid >> 5;
    const int lane = tid & 31;
    const int rowbase = blockIdx.x * BM;
    const int Rw = (wid & 3) * 32;      // 4 warps over M=128
    const int Cw = (wid >> 2) * 16;     // 4 warps over N=64

    if (tid < BM) {
        rowMin[tid] = 0x7f7fffff;
        cnt[tid] = 0;
        z2s[tid] = g_z2[rowbase + tid];
    }
    const u32 mb0 = smb + SMBAR, mb1 = smb + SMBAR + 8, mbA = smb + SMBAR + 16;
    if (tid == 0) { MBAR_INIT(mb0, 1); MBAR_INIT(mb1, 1); MBAR_INIT(mbA, 1); }
    __syncthreads();

    if (tid == 0) {
        EXPECT_TX(mbA, BM * 512);
        BULK_G2S(smb + SA, (const char*)(g_zbf4 + (size_t)rowbase * 32), BM * 512, mbA);
        EXPECT_TX(mb0, BN * 512);
        BULK_G2S(smb + SB0, (const char*)g_ebf4, BN * 512, mb0);
    }
    mbar_wait(mbA, 0);

    // ldmatrix lane geometry (pre-swizzled layout: chunk index ^= row&7)
    const int lrA  = (lane & 7) + 8 * ((lane >> 3) & 1);
    const int khA  = lane >> 4;
    const int rowA = Rw + lrA;
    const u32 baseA = smb + SA + (u32)rowA * 512;
    const int xA   = rowA & 7;
    const int lrB  = (lane & 7) + 8 * (lane >> 4);
    const int khB  = (lane >> 3) & 1;
    const int rowB = Cw + lrB;
    const u32 offB = (u32)rowB * 512;
    const int xB   = rowB & 7;

    for (int t = 0; t < NTILES; ++t) {
        if (t + 1 < NTILES && tid == 0) {
            u32 mb = ((t + 1) & 1) ? mb1 : mb0;
            EXPECT_TX(mb, BN * 512);
            BULK_G2S(smb + (((t + 1) & 1) ? SB1 : SB0),
                     (const char*)(g_ebf4 + (size_t)(t + 1) * BN * 32), BN * 512, mb);
        }
        mbar_wait((t & 1) ? mb1 : mb0, (t >> 1) & 1);

        const u32 baseB = smb + ((t & 1) ? SB1 : SB0) + offB;

        float acc[2][2][4];
        #pragma unroll
        for (int mi = 0; mi < 2; ++mi)
            #pragma unroll
            for (int ni = 0; ni < 2; ++ni)
                #pragma unroll
                for (int c = 0; c < 4; ++c) acc[mi][ni][c] = 0.f;

        #pragma unroll 4
        for (int ks = 0; ks < 16; ++ks) {
            u32 aT[2][4], bT[4];
            u32 ca  = (u32)(((2 * ks + khA) ^ xA) << 4);
            u32 cb2 = (u32)(((2 * ks + khB) ^ xB) << 4);
            ldsm4(aT[0], baseA + ca);
            ldsm4(aT[1], baseA + 8192 + ca);
            ldsm4(bT,    baseB + cb2);
            #pragma unroll
            for (int mi = 0; mi < 2; ++mi) {
                mma16816(acc[mi][0], aT[mi], &bT[0]);
                mma16816(acc[mi][1], aT[mi], &bT[2]);
            }
        }

        // ---- epilogue: dv in-place, row-min update, windowed inserts ----
        int cb = t * BN;
        float e2loc[2][2];
        #pragma unroll
        for (int ni = 0; ni < 2; ++ni) {
            float2 v = __ldg((const float2*)(g_e2 + cb + Cw + ni * 8 + (lane & 3) * 2));
            e2loc[ni][0] = v.x; e2loc[ni][1] = v.y;
        }
        #pragma unroll
        for (int mi = 0; mi < 2; ++mi) {
            #pragma unroll
            for (int s = 0; s < 2; ++s) {
                int r = Rw + mi * 16 + (lane >> 2) + 8 * s;
                float z2v = z2s[r];
                float mn = 3.4e38f;
                #pragma unroll
                for (int ni = 0; ni < 2; ++ni) {
                    #pragma unroll
                    for (int q = 0; q < 2; ++q) {
                        float dv = fmaf(-2.f, acc[mi][ni][2 * s + q], z2v + e2loc[ni][q]);
                        acc[mi][ni][2 * s + q] = dv;
                        mn = fminf(mn, dv);
                    }
                }
                if (__float_as_int(mn) < rowMin[r])
                    atomicMin(&rowMin[r], __float_as_int(mn));
            }
        }
        if (t == 0) __syncthreads();   // tile 0: establish thresholds first
        #pragma unroll
        for (int mi = 0; mi < 2; ++mi) {
            #pragma unroll
            for (int s = 0; s < 2; ++s) {
                int r = Rw + mi * 16 + (lane >> 2) + 8 * s;
                float thr = __int_as_float(rowMin[r]) + WIN;
                #pragma unroll
                for (int ni = 0; ni < 2; ++ni) {
                    #pragma unroll
                    for (int q = 0; q < 2; ++q) {
                        float dv = acc[mi][ni][2 * s + q];
                        if (dv <= thr) {
                            int pos = atomicAdd(&cnt[r], 1);
                            if (pos < CAP) {
                                candD[r * CAP + pos] = dv;
                                candK[r * CAP + pos] = cb + Cw + ni * 8 + (lane & 3) * 2 + q;
                            }
                        }
                    }
                }
            }
        }
        __syncthreads();
    }

    // ---- exact rescore (replicates R2 arithmetic exactly) ----
    if (tid < BM) {
        int r = tid;
        size_t n = (size_t)rowbase + r;
        int c = cnt[r];
        if (c > CAP) {
            fidx[r] = -1;
        } else {
            float thrF = __int_as_float(rowMin[r]) + WIN;
            float z2e = g_z2[n];
            const float* zr = z + n * DD;
            float bd = 0.f; int bk = -1;
            for (int i = 0; i < c; ++i) {
                if (candD[r * CAP + i] > thrF) continue;
                int k = candK[r * CAP + i];
                const float* er = emb + (size_t)k * DD;
                float lo = 0.f, hi = 0.f;
                #pragma unroll 4
                for (int d2 = 0; d2 < DD / 2; ++d2) {
                    lo = __fmaf_rn(__ldg(zr + 2 * d2),     __ldg(er + 2 * d2),     lo);
                    hi = __fmaf_rn(__ldg(zr + 2 * d2 + 1), __ldg(er + 2 * d2 + 1), hi);
                }
                float dot = __fadd_rn(lo, hi);
                float tt  = __fadd_rn(z2e, g_e2[k]);
                float dd  = __fadd_rn(tt, -2.0f * dot);
                if (bk < 0 || dd < bd || (dd == bd && k < bk)) { bd = dd; bk = k; }
            }
            fidx[r] = bk;
        }
    }
    __syncthreads();

    // ---- overflow fallback: full exact scan (cold with CAP=40) ----
    {
        float* redD = (float*)(sm + SB0);
        int*   redI = (int*)(sm + SB0 + NTHR * 4);
        for (int r = 0; r < BM; ++r) {
            if (fidx[r] != -1) continue;
            size_t n = (size_t)rowbase + r;
            const float* zr = z + n * DD;
            float z2e = g_z2[n];
            float bd = 0.f; int bk = -1;
            for (int k = tid; k < KC; k += NTHR) {
                const float* er = emb + (size_t)k * DD;
                float lo = 0.f, hi = 0.f;
                #pragma unroll 4
                for (int d2 = 0; d2 < DD / 2; ++d2) {
                    lo = __fmaf_rn(zr[2 * d2],     er[2 * d2],     lo);
                    hi = __fmaf_rn(zr[2 * d2 + 1], er[2 * d2 + 1], hi);
                }
                float dot = __fadd_rn(lo, hi);
                float dd  = __fadd_rn(__fadd_rn(z2e, g_e2[k]), -2.0f * dot);
                if (bk < 0 || dd < bd || (dd == bd && k < bk)) { bd = dd; bk = k; }
            }
            redD[tid] = bd; redI[tid] = bk;
            __syncthreads();
            if (tid == 0) {
                float B = redD[0]; int K2 = redI[0];
                for (int s2 = 1; s2 < NTHR; ++s2) {
                    float d = redD[s2]; int k2 = redI[s2];
                    if (k2 >= 0 && (K2 < 0 || d < B || (d == B && k2 < K2))) { B = d; K2 = k2; }
                }
                fidx[r] = K2;
            }
            __syncthreads();
        }
    }
    __syncthreads();

    // ---- outputs (512 threads: 2 rows per pass) ----
    for (int rr = 0; rr < BM; rr += 2) {
        int    r   = rr + (tid >> 8);
        int    c   = tid & 255;
        int    idx = fidx[r];
        size_t n   = (size_t)rowbase + r;
        float  qv  = __ldg(emb + (size_t)idx * DD + c);
        float  zv  = __ldg(z + n * DD + c);
        if (oq)  oq[n * DD + c]  = qv;
        if (ost) ost[n * DD + c] = __fadd_rn(__fadd_rn(qv, -zv), zv);
    }
    if (oidx && tid < BM)
        oidx[(size_t)rowbase + tid] = (float)fidx[tid];
}

extern "C" void kernel_launch(void* const* d_in, const int* in_sizes, int n_in,
                              void* d_out, int out_size)
{
    const float* z   = (const float*)d_in[0];
    const float* emb = (const float*)d_in[1];
    float* out = (float*)d_out;

    const int N = in_sizes[0] / DD;
    const size_t ND = (size_t)N * DD;

    float *oq = nullptr, *ost = nullptr, *oidx = nullptr;
    long osz = (long)out_size;
    if (osz >= (long)(2 * ND + N)) { oq = out; ost = out + ND; oidx = out + 2 * ND; }
    else if (osz == (long)(ND + N)) { oq = out; oidx = out + ND; }
    else if (osz == (long)ND)       { oq = out; }
    else if (osz == (long)N)        { oidx = out; }
    else                            { oq = out; }

    prep_all<<<KC + N, 32>>>(z, emb);

    cudaFuncSetAttribute(vq_main, cudaFuncAttributeMaxDynamicSharedMemorySize, STOT);
    vq_main<<<N / BM, NTHR, STOT>>>(z, emb, oq, ost, oidx);
}